// round 15
// baseline (speedup 1.0000x reference)
#include <cuda_runtime.h>
#include <cuda_fp16.h>
#include <cstdint>

// Problem constants (match reference_code)
#define N_ITEMS 100000
#define N_USERS 40000
#define N_TOTAL (N_ITEMS + N_USERS)     // 140000 combined row space
#define EMB     100
#define ROW4    25                      // uint2 (4 halves) per row
#define NNZ_A   3200000
#define NNZ_U   1600000
#define NNZ_T   (NNZ_A + NNZ_U)         // 4.8M combined edges
#define BATCH   4096

#define SCAN_TPB 256
#define NB_T ((N_TOTAL + SCAN_TPB - 1) / SCAN_TPB)   // 547

// ---------------------------------------------------------------------------
// Device scratch (no allocations allowed)
// ---------------------------------------------------------------------------
__device__ uint2 g_eh[(size_t)N_ITEMS * ROW4];  // 20 MB fp16 embedding
__device__ uint2 g_h0[(size_t)N_ITEMS * ROW4];  // 20 MB fp16 x1
__device__ uint2 g_h1[(size_t)N_ITEMS * ROW4];  // 20 MB fp16 x2
__device__ int   g_cnt[N_TOTAL];                // combined histogram
__device__ int   g_ptr[N_TOTAL];                // combined exclusive offsets
__device__ int   g_run[N_TOTAL];                // scatter cursors
__device__ int2  g_cv[NNZ_T];                   // row-sorted (col, val-bits)
__device__ int   g_bsum[1024];
__device__ int   g_uflag[N_USERS];              // user-in-batch flag

// ---------------------------------------------------------------------------
// mark users that appear in the batch (g_uflag zeroed by memset beforehand)
// ---------------------------------------------------------------------------
__global__ void __launch_bounds__(256) k_flag(const int* __restrict__ user) {
    int i = blockIdx.x * blockDim.x + threadIdx.x;
    if (i < BATCH) g_uflag[user[i]] = 1;
}

// ---------------------------------------------------------------------------
// fused: fp16 embedding conversion + combined histogram (fire-and-forget RED).
// U-edges are flag-gated: unflagged user rows get cnt=0 (empty CSR ranges,
// never read by k_user_batch). Flagged rows get exact full counts.
// g_cnt must be zeroed beforehand (cudaMemsetAsync in kernel_launch).
// ---------------------------------------------------------------------------
__global__ void __launch_bounds__(256) k_prep_hist(const float4* __restrict__ emb,
                                                   const int* __restrict__ rowsA,
                                                   const int* __restrict__ rowsU) {
    int i = blockIdx.x * blockDim.x + threadIdx.x;
    if (i < N_ITEMS * ROW4) {
        float4 v = emb[i];
        __half2 lo = __floats2half2_rn(v.x, v.y);
        __half2 hi = __floats2half2_rn(v.z, v.w);
        uint2 h;
        h.x = *reinterpret_cast<uint32_t*>(&lo);
        h.y = *reinterpret_cast<uint32_t*>(&hi);
        g_eh[i] = h;
    }
    if (i < NNZ_A) {
        atomicAdd(&g_cnt[rowsA[i]], 1);
    } else if (i < NNZ_T) {
        int r = rowsU[i - NNZ_A];
        if (g_uflag[r]) atomicAdd(&g_cnt[N_ITEMS + r], 1);
    }
}

// ---------------------------------------------------------------------------
// scan phase 1: per-block exclusive scan, block totals into bsum
// ---------------------------------------------------------------------------
__global__ void __launch_bounds__(SCAN_TPB) k_scan1(const int* __restrict__ cnt,
                                                    int* __restrict__ ptr,
                                                    int* __restrict__ bsum, int n) {
    __shared__ int sh[SCAN_TPB];
    int tid = threadIdx.x;
    int i = blockIdx.x * SCAN_TPB + tid;
    int v = (i < n) ? cnt[i] : 0;
    sh[tid] = v;
    __syncthreads();
    for (int off = 1; off < SCAN_TPB; off <<= 1) {
        int t = (tid >= off) ? sh[tid - off] : 0;
        __syncthreads();
        sh[tid] += t;
        __syncthreads();
    }
    if (i < n) ptr[i] = sh[tid] - v;
    if (tid == SCAN_TPB - 1) bsum[blockIdx.x] = sh[tid];
}

// ---------------------------------------------------------------------------
// scan phase 2: each block computes its own prefix over bsum[0..b-1], then
// finalizes its ptr slice and mirrors into run (scatter cursors).
// ---------------------------------------------------------------------------
__global__ void __launch_bounds__(SCAN_TPB) k_scan23(int* __restrict__ ptr,
                                                     int* __restrict__ run,
                                                     const int* __restrict__ bsum, int n) {
    __shared__ int sh[SCAN_TPB];
    int tid = threadIdx.x;
    int b   = blockIdx.x;

    int s = 0;
    for (int t = tid; t < b; t += SCAN_TPB) s += __ldg(&bsum[t]);
    sh[tid] = s;
    __syncthreads();
    #pragma unroll
    for (int off = SCAN_TPB / 2; off > 0; off >>= 1) {
        if (tid < off) sh[tid] += sh[tid + off];
        __syncthreads();
    }
    int prefix = sh[0];

    int i = b * SCAN_TPB + tid;
    if (i < n) {
        int p = ptr[i] + prefix;
        ptr[i] = p;
        run[i] = p;
    }
}

// ---------------------------------------------------------------------------
// scatter: A edges unconditional; U edges only when their user row is in the
// batch (flag gate skips ~90% of U atomics+stores).
// ---------------------------------------------------------------------------
__global__ void __launch_bounds__(256) k_scatter(
        const int* __restrict__ rowsA, const int* __restrict__ colsA,
        const float* __restrict__ valsA,
        const int* __restrict__ rowsU, const int* __restrict__ colsU,
        const float* __restrict__ valsU) {
    int e = blockIdx.x * blockDim.x + threadIdx.x;
    if (e < NNZ_A) {
        int pos = atomicAdd(&g_run[rowsA[e]], 1);
        g_cv[pos] = make_int2(colsA[e], __float_as_int(valsA[e]));
    } else if (e < NNZ_T) {
        int eu = e - NNZ_A;
        int r  = rowsU[eu];
        if (g_uflag[r]) {
            int pos = atomicAdd(&g_run[N_ITEMS + r], 1);
            g_cv[pos] = make_int2(colsU[eu], __float_as_int(valsU[eu]));
        }
    }
}

// ---------------------------------------------------------------------------
// fp16 helpers
// ---------------------------------------------------------------------------
__device__ __forceinline__ void fma_h4(float4& acc, uint2 h, float v) {
    __half2 lo = *reinterpret_cast<__half2*>(&h.x);
    __half2 hi = *reinterpret_cast<__half2*>(&h.y);
    float2 a = __half22float2(lo);
    float2 b = __half22float2(hi);
    acc.x += v * a.x; acc.y += v * a.y;
    acc.z += v * b.x; acc.w += v * b.y;
}

__device__ __forceinline__ float4 h4_to_f4(uint2 h) {
    __half2 lo = *reinterpret_cast<__half2*>(&h.x);
    __half2 hi = *reinterpret_cast<__half2*>(&h.y);
    float2 a = __half22float2(lo);
    float2 b = __half22float2(hi);
    return make_float4(a.x, a.y, b.x, b.y);
}

// ---------------------------------------------------------------------------
// shared CSR gather loop body (unroll-8, front-batched loads for MLP)
// ---------------------------------------------------------------------------
__device__ __forceinline__ float4 csr_row_gather(const uint2* __restrict__ xh,
                                                 int e, int end, int lane,
                                                 bool active) {
    float4 acc = make_float4(0.f, 0.f, 0.f, 0.f);
    for (; e + 7 < end; e += 8) {
        int2 p[8];
        #pragma unroll
        for (int j = 0; j < 8; j++) p[j] = __ldg(&g_cv[e + j]);
        if (active) {
            uint2 h[8];
            #pragma unroll
            for (int j = 0; j < 8; j++) h[j] = __ldg(&xh[p[j].x * ROW4 + lane]);
            #pragma unroll
            for (int j = 0; j < 8; j++) fma_h4(acc, h[j], __int_as_float(p[j].y));
        }
    }
    if (e + 3 < end) {
        int2 p[4];
        #pragma unroll
        for (int j = 0; j < 4; j++) p[j] = __ldg(&g_cv[e + j]);
        if (active) {
            uint2 h[4];
            #pragma unroll
            for (int j = 0; j < 4; j++) h[j] = __ldg(&xh[p[j].x * ROW4 + lane]);
            #pragma unroll
            for (int j = 0; j < 4; j++) fma_h4(acc, h[j], __int_as_float(p[j].y));
        }
        e += 4;
    }
    for (; e < end; e++) {
        int2 p0 = __ldg(&g_cv[e]);
        if (active) {
            uint2 a = __ldg(&xh[p0.x * ROW4 + lane]);
            fma_h4(acc, a, __int_as_float(p0.y));
        }
    }
    return acc;
}

// ---------------------------------------------------------------------------
// CSR SpMM layers 1,2: warp per row, fp16 in, fp32 accum, fp16 out
// ---------------------------------------------------------------------------
__global__ void __launch_bounds__(256) k_spmm_h(const uint2* __restrict__ xh,
                                                uint2* __restrict__ dsth) {
    int w = (blockIdx.x * blockDim.x + threadIdx.x) >> 5;
    int lane = threadIdx.x & 31;
    if (w >= N_ITEMS) return;

    int e   = __ldg(&g_ptr[w]);
    int end = __ldg(&g_ptr[w + 1]);     // w+1 <= N_ITEMS < N_TOTAL always valid
    bool active = lane < ROW4;

    float4 acc = csr_row_gather(xh, e, end, lane, active);

    if (active) {
        __half2 lo = __floats2half2_rn(acc.x, acc.y);
        __half2 hi = __floats2half2_rn(acc.z, acc.w);
        uint2 h;
        h.x = *reinterpret_cast<uint32_t*>(&lo);
        h.y = *reinterpret_cast<uint32_t*>(&hi);
        dsth[w * ROW4 + lane] = h;
    }
}

// ---------------------------------------------------------------------------
// Layer 3 (final): acc = A @ x2 ; total = emb + x1 + x2 + acc  (fp32 out)
// ---------------------------------------------------------------------------
__global__ void __launch_bounds__(256) k_spmm_final(const uint2* __restrict__ x2h,
                                                    const uint2* __restrict__ x1h,
                                                    const float4* __restrict__ emb,
                                                    float4* __restrict__ total) {
    int w = (blockIdx.x * blockDim.x + threadIdx.x) >> 5;
    int lane = threadIdx.x & 31;
    if (w >= N_ITEMS) return;

    int e   = __ldg(&g_ptr[w]);
    int end = __ldg(&g_ptr[w + 1]);
    bool active = lane < ROW4;

    float4 acc = csr_row_gather(x2h, e, end, lane, active);

    if (active) {
        int idx = w * ROW4 + lane;
        float4 t  = __ldg(&emb[idx]);
        float4 x1 = h4_to_f4(__ldg(&x1h[idx]));
        float4 x2 = h4_to_f4(__ldg(&x2h[idx]));
        t.x += x1.x + x2.x + acc.x;
        t.y += x1.y + x2.y + acc.y;
        t.z += x1.z + x2.z + acc.z;
        t.w += x1.w + x2.w + acc.w;
        total[idx] = t;
    }
}

// ---------------------------------------------------------------------------
// user batch: out2[b] = sum over CSR row (N_ITEMS + user[b]) of val * total[col]
// fp32 gathers of total, unroll-8 front-batched. Only flagged rows are read,
// and flagged rows received ALL their edges (exact counts + full scatter).
// ---------------------------------------------------------------------------
__global__ void __launch_bounds__(256) k_user_batch(const float4* __restrict__ total,
                                                    const int* __restrict__ user,
                                                    float4* __restrict__ out2) {
    int w = (blockIdx.x * blockDim.x + threadIdx.x) >> 5;
    int lane = threadIdx.x & 31;
    if (w >= BATCH) return;

    int u   = N_ITEMS + __ldg(&user[w]);
    int e   = __ldg(&g_ptr[u]);
    int end = (u + 1 < N_TOTAL) ? __ldg(&g_ptr[u + 1]) : NNZ_T;
    bool active = lane < ROW4;

    float4 acc = make_float4(0.f, 0.f, 0.f, 0.f);
    for (; e + 7 < end; e += 8) {
        int2 p[8];
        #pragma unroll
        for (int j = 0; j < 8; j++) p[j] = __ldg(&g_cv[e + j]);
        if (active) {
            float4 h[8];
            #pragma unroll
            for (int j = 0; j < 8; j++) h[j] = __ldg(&total[p[j].x * ROW4 + lane]);
            #pragma unroll
            for (int j = 0; j < 8; j++) {
                float v = __int_as_float(p[j].y);
                acc.x += v * h[j].x; acc.y += v * h[j].y;
                acc.z += v * h[j].z; acc.w += v * h[j].w;
            }
        }
    }
    for (; e < end; e++) {
        int2 p0 = __ldg(&g_cv[e]);
        if (active) {
            float v0 = __int_as_float(p0.y);
            float4 a = __ldg(&total[p0.x * ROW4 + lane]);
            acc.x += v0 * a.x; acc.y += v0 * a.y;
            acc.z += v0 * a.z; acc.w += v0 * a.w;
        }
    }
    if (active) out2[w * ROW4 + lane] = acc;
}

// ---------------------------------------------------------------------------
// Inputs (metadata order):
//  0 adj_vals f32[3.2M]   1 u_vals f32[1.6M]   2 embedding f32[100000,100]
//  3 user_embedding f32[40000,100]             4 adj_rows i32  5 adj_cols i32
//  6 u_rows i32  7 u_cols i32  8 user i32[4096]
// Output: concat(total [100000*100], user_all[user] [4096*100]) as f32
// ---------------------------------------------------------------------------
extern "C" void kernel_launch(void* const* d_in, const int* in_sizes, int n_in,
                              void* d_out, int out_size) {
    const float* adj_vals = (const float*)d_in[0];
    const float* u_vals   = (const float*)d_in[1];
    const float* emb      = (const float*)d_in[2];
    const int*   adj_rows = (const int*)d_in[4];
    const int*   adj_cols = (const int*)d_in[5];
    const int*   u_rows   = (const int*)d_in[6];
    const int*   u_cols   = (const int*)d_in[7];
    const int*   user     = (const int*)d_in[8];

    float* total = (float*)d_out;                    // [N_ITEMS*EMB]
    float* out2  = total + (size_t)N_ITEMS * EMB;    // [BATCH*EMB]

    uint2 *eh, *h0, *h1;
    int *cnt, *ptr, *run, *bsum, *uflag;
    cudaGetSymbolAddress((void**)&eh,    g_eh);
    cudaGetSymbolAddress((void**)&h0,    g_h0);
    cudaGetSymbolAddress((void**)&h1,    g_h1);
    cudaGetSymbolAddress((void**)&cnt,   g_cnt);
    cudaGetSymbolAddress((void**)&ptr,   g_ptr);
    cudaGetSymbolAddress((void**)&run,   g_run);
    cudaGetSymbolAddress((void**)&bsum,  g_bsum);
    cudaGetSymbolAddress((void**)&uflag, g_uflag);

    const int TPB = 256;

    // ---- zero histogram + user flags (graph-capturable memset nodes) ----
    cudaMemsetAsync(cnt, 0, N_TOTAL * sizeof(int));
    cudaMemsetAsync(uflag, 0, N_USERS * sizeof(int));
    k_flag<<<(BATCH + TPB - 1) / TPB, TPB>>>(user);

    // ---- fused fp16 conversion + flag-gated histogram ----
    k_prep_hist<<<(NNZ_T + TPB - 1) / TPB, TPB>>>((const float4*)emb,
                                                  adj_rows, u_rows);

    // ---- 2-kernel scan + flag-gated scatter (unified CSR) ----
    k_scan1<<<NB_T, SCAN_TPB>>>(cnt, ptr, bsum, N_TOTAL);
    k_scan23<<<NB_T, SCAN_TPB>>>(ptr, run, bsum, N_TOTAL);
    k_scatter<<<(NNZ_T + TPB - 1) / TPB, TPB>>>(adj_rows, adj_cols, adj_vals,
                                                u_rows, u_cols, u_vals);

    // ---- 3 propagation layers (warp per row, fp16 gathers, fp32 accum) ----
    const int spmm_blocks = (N_ITEMS * 32 + TPB - 1) / TPB;
    k_spmm_h<<<spmm_blocks, TPB>>>(eh, h0);                            // x1
    k_spmm_h<<<spmm_blocks, TPB>>>(h0, h1);                            // x2
    k_spmm_final<<<spmm_blocks, TPB>>>(h1, h0, (const float4*)emb,
                                       (float4*)total);                // total

    // ---- user projection, batch rows only ----
    const int ub_blocks = (BATCH * 32 + TPB - 1) / TPB;
    k_user_batch<<<ub_blocks, TPB>>>((const float4*)total, user, (float4*)out2);
}

// round 16
// speedup vs baseline: 284.7234x; 284.7234x over previous
#include <cuda_runtime.h>
#include <cuda_fp16.h>
#include <cstdint>

// Problem constants (match reference_code)
#define N_ITEMS 100000
#define N_USERS 40000
#define N_TOTAL (N_ITEMS + N_USERS)     // 140000 combined row space
#define EMB     100
#define ROW4    25                      // uint2 (4 halves) per row
#define NNZ_A   3200000
#define NNZ_U   1600000
#define NNZ_T   (NNZ_A + NNZ_U)         // 4.8M combined edges
#define BATCH   4096

#define SCAN_TPB 256
#define NB_T ((N_TOTAL + SCAN_TPB - 1) / SCAN_TPB)   // 547

// ---------------------------------------------------------------------------
// Device scratch (no allocations allowed)
// ---------------------------------------------------------------------------
__device__ uint2 g_eh[(size_t)N_ITEMS * ROW4];  // 20 MB fp16 embedding
__device__ uint2 g_h0[(size_t)N_ITEMS * ROW4];  // 20 MB fp16 x1
__device__ uint2 g_h1[(size_t)N_ITEMS * ROW4];  // 20 MB fp16 x2
__device__ int   g_cnt[N_TOTAL];                // combined histogram
__device__ int   g_ptr[N_TOTAL + 1];            // exclusive offsets + total
__device__ int   g_run[N_TOTAL];                // scatter cursors
__device__ int2  g_cv[NNZ_T];                   // row-sorted (col, val-bits)
__device__ int   g_bsum[1024];
__device__ int   g_uflag[N_USERS];              // user-in-batch flag

// ---------------------------------------------------------------------------
// mark users that appear in the batch (g_uflag zeroed by memset beforehand)
// ---------------------------------------------------------------------------
__global__ void __launch_bounds__(256) k_flag(const int* __restrict__ user) {
    int i = blockIdx.x * blockDim.x + threadIdx.x;
    if (i < BATCH) g_uflag[user[i]] = 1;
}

// ---------------------------------------------------------------------------
// fused: fp16 embedding conversion + combined histogram (fire-and-forget RED).
// Histogram is UNGATED (hist-gating measured 2x catastrophic: R7, R15).
// g_cnt must be zeroed beforehand (cudaMemsetAsync in kernel_launch).
// ---------------------------------------------------------------------------
__global__ void __launch_bounds__(256) k_prep_hist(const float4* __restrict__ emb,
                                                   const int* __restrict__ rowsA,
                                                   const int* __restrict__ rowsU) {
    int i = blockIdx.x * blockDim.x + threadIdx.x;
    if (i < N_ITEMS * ROW4) {
        float4 v = emb[i];
        __half2 lo = __floats2half2_rn(v.x, v.y);
        __half2 hi = __floats2half2_rn(v.z, v.w);
        uint2 h;
        h.x = *reinterpret_cast<uint32_t*>(&lo);
        h.y = *reinterpret_cast<uint32_t*>(&hi);
        g_eh[i] = h;
    }
    if (i < NNZ_A)            atomicAdd(&g_cnt[rowsA[i]], 1);
    else if (i < NNZ_T)       atomicAdd(&g_cnt[N_ITEMS + rowsU[i - NNZ_A]], 1);
}

// ---------------------------------------------------------------------------
// scan phase 1: per-block exclusive scan, block totals into bsum
// ---------------------------------------------------------------------------
__global__ void __launch_bounds__(SCAN_TPB) k_scan1(const int* __restrict__ cnt,
                                                    int* __restrict__ ptr,
                                                    int* __restrict__ bsum, int n) {
    __shared__ int sh[SCAN_TPB];
    int tid = threadIdx.x;
    int i = blockIdx.x * SCAN_TPB + tid;
    int v = (i < n) ? cnt[i] : 0;
    sh[tid] = v;
    __syncthreads();
    for (int off = 1; off < SCAN_TPB; off <<= 1) {
        int t = (tid >= off) ? sh[tid - off] : 0;
        __syncthreads();
        sh[tid] += t;
        __syncthreads();
    }
    if (i < n) ptr[i] = sh[tid] - v;
    if (tid == SCAN_TPB - 1) bsum[blockIdx.x] = sh[tid];
}

// ---------------------------------------------------------------------------
// scan phase 2: each block computes its own prefix over bsum[0..b-1], then
// finalizes its ptr slice and mirrors into run. The last block also writes
// the grand total into ptr[n] so consumers never need an NNZ literal.
// ---------------------------------------------------------------------------
__global__ void __launch_bounds__(SCAN_TPB) k_scan23(int* __restrict__ ptr,
                                                     int* __restrict__ run,
                                                     const int* __restrict__ bsum, int n) {
    __shared__ int sh[SCAN_TPB];
    int tid = threadIdx.x;
    int b   = blockIdx.x;
    int nb  = gridDim.x;

    // inclusive sum over bsum[0..b] so the last block can emit the total;
    // prefix (exclusive of own block) = incl - bsum[b]
    int s = 0;
    for (int t = tid; t <= b; t += SCAN_TPB) s += __ldg(&bsum[t]);
    sh[tid] = s;
    __syncthreads();
    #pragma unroll
    for (int off = SCAN_TPB / 2; off > 0; off >>= 1) {
        if (tid < off) sh[tid] += sh[tid + off];
        __syncthreads();
    }
    int incl   = sh[0];
    int prefix = incl - __ldg(&bsum[b]);

    int i = b * SCAN_TPB + tid;
    if (i < n) {
        int p = ptr[i] + prefix;
        ptr[i] = p;
        run[i] = p;
    }
    if (b == nb - 1 && tid == 0) ptr[n] = incl;   // grand total
}

// ---------------------------------------------------------------------------
// scatter: A edges unconditional; U edges only when their user row is in the
// batch (flag gate skips ~90% of U atomics+stores; unread rows stay stale).
// ---------------------------------------------------------------------------
__global__ void __launch_bounds__(256) k_scatter(
        const int* __restrict__ rowsA, const int* __restrict__ colsA,
        const float* __restrict__ valsA,
        const int* __restrict__ rowsU, const int* __restrict__ colsU,
        const float* __restrict__ valsU) {
    int e = blockIdx.x * blockDim.x + threadIdx.x;
    if (e < NNZ_A) {
        int pos = atomicAdd(&g_run[rowsA[e]], 1);
        g_cv[pos] = make_int2(colsA[e], __float_as_int(valsA[e]));
    } else if (e < NNZ_T) {
        int eu = e - NNZ_A;
        int r  = rowsU[eu];
        if (g_uflag[r]) {
            int pos = atomicAdd(&g_run[N_ITEMS + r], 1);
            g_cv[pos] = make_int2(colsU[eu], __float_as_int(valsU[eu]));
        }
    }
}

// ---------------------------------------------------------------------------
// fp16 helpers
// ---------------------------------------------------------------------------
__device__ __forceinline__ void fma_h4(float4& acc, uint2 h, float v) {
    __half2 lo = *reinterpret_cast<__half2*>(&h.x);
    __half2 hi = *reinterpret_cast<__half2*>(&h.y);
    float2 a = __half22float2(lo);
    float2 b = __half22float2(hi);
    acc.x += v * a.x; acc.y += v * a.y;
    acc.z += v * b.x; acc.w += v * b.y;
}

__device__ __forceinline__ float4 h4_to_f4(uint2 h) {
    __half2 lo = *reinterpret_cast<__half2*>(&h.x);
    __half2 hi = *reinterpret_cast<__half2*>(&h.y);
    float2 a = __half22float2(lo);
    float2 b = __half22float2(hi);
    return make_float4(a.x, a.y, b.x, b.y);
}

// ---------------------------------------------------------------------------
// shared CSR gather loop body (unroll-8, front-batched loads for MLP)
// ---------------------------------------------------------------------------
__device__ __forceinline__ float4 csr_row_gather(const uint2* __restrict__ xh,
                                                 int e, int end, int lane,
                                                 bool active) {
    float4 acc = make_float4(0.f, 0.f, 0.f, 0.f);
    for (; e + 7 < end; e += 8) {
        int2 p[8];
        #pragma unroll
        for (int j = 0; j < 8; j++) p[j] = __ldg(&g_cv[e + j]);
        if (active) {
            uint2 h[8];
            #pragma unroll
            for (int j = 0; j < 8; j++) h[j] = __ldg(&xh[p[j].x * ROW4 + lane]);
            #pragma unroll
            for (int j = 0; j < 8; j++) fma_h4(acc, h[j], __int_as_float(p[j].y));
        }
    }
    if (e + 3 < end) {
        int2 p[4];
        #pragma unroll
        for (int j = 0; j < 4; j++) p[j] = __ldg(&g_cv[e + j]);
        if (active) {
            uint2 h[4];
            #pragma unroll
            for (int j = 0; j < 4; j++) h[j] = __ldg(&xh[p[j].x * ROW4 + lane]);
            #pragma unroll
            for (int j = 0; j < 4; j++) fma_h4(acc, h[j], __int_as_float(p[j].y));
        }
        e += 4;
    }
    for (; e < end; e++) {
        int2 p0 = __ldg(&g_cv[e]);
        if (active) {
            uint2 a = __ldg(&xh[p0.x * ROW4 + lane]);
            fma_h4(acc, a, __int_as_float(p0.y));
        }
    }
    return acc;
}

// ---------------------------------------------------------------------------
// CSR SpMM layers 1,2: warp per row, fp16 in, fp32 accum, fp16 out
// ---------------------------------------------------------------------------
__global__ void __launch_bounds__(256) k_spmm_h(const uint2* __restrict__ xh,
                                                uint2* __restrict__ dsth) {
    int w = (blockIdx.x * blockDim.x + threadIdx.x) >> 5;
    int lane = threadIdx.x & 31;
    if (w >= N_ITEMS) return;

    int e   = __ldg(&g_ptr[w]);
    int end = __ldg(&g_ptr[w + 1]);
    bool active = lane < ROW4;

    float4 acc = csr_row_gather(xh, e, end, lane, active);

    if (active) {
        __half2 lo = __floats2half2_rn(acc.x, acc.y);
        __half2 hi = __floats2half2_rn(acc.z, acc.w);
        uint2 h;
        h.x = *reinterpret_cast<uint32_t*>(&lo);
        h.y = *reinterpret_cast<uint32_t*>(&hi);
        dsth[w * ROW4 + lane] = h;
    }
}

// ---------------------------------------------------------------------------
// Layer 3 (final): acc = A @ x2 ; total = emb + x1 + x2 + acc  (fp32 out)
// ---------------------------------------------------------------------------
__global__ void __launch_bounds__(256) k_spmm_final(const uint2* __restrict__ x2h,
                                                    const uint2* __restrict__ x1h,
                                                    const float4* __restrict__ emb,
                                                    float4* __restrict__ total) {
    int w = (blockIdx.x * blockDim.x + threadIdx.x) >> 5;
    int lane = threadIdx.x & 31;
    if (w >= N_ITEMS) return;

    int e   = __ldg(&g_ptr[w]);
    int end = __ldg(&g_ptr[w + 1]);
    bool active = lane < ROW4;

    float4 acc = csr_row_gather(x2h, e, end, lane, active);

    if (active) {
        int idx = w * ROW4 + lane;
        float4 t  = __ldg(&emb[idx]);
        float4 x1 = h4_to_f4(__ldg(&x1h[idx]));
        float4 x2 = h4_to_f4(__ldg(&x2h[idx]));
        t.x += x1.x + x2.x + acc.x;
        t.y += x1.y + x2.y + acc.y;
        t.z += x1.z + x2.z + acc.z;
        t.w += x1.w + x2.w + acc.w;
        total[idx] = t;
    }
}

// ---------------------------------------------------------------------------
// user batch: out2[b] = sum over CSR row (N_ITEMS + user[b]) of val * total[col]
// fp32 gathers of total, unroll-8 front-batched. ptr[u+1] is always valid
// (ptr has N_TOTAL+1 entries; last one holds the grand total).
// ---------------------------------------------------------------------------
__global__ void __launch_bounds__(256) k_user_batch(const float4* __restrict__ total,
                                                    const int* __restrict__ user,
                                                    float4* __restrict__ out2) {
    int w = (blockIdx.x * blockDim.x + threadIdx.x) >> 5;
    int lane = threadIdx.x & 31;
    if (w >= BATCH) return;

    int u   = N_ITEMS + __ldg(&user[w]);
    int e   = __ldg(&g_ptr[u]);
    int end = __ldg(&g_ptr[u + 1]);
    bool active = lane < ROW4;

    float4 acc = make_float4(0.f, 0.f, 0.f, 0.f);
    for (; e + 7 < end; e += 8) {
        int2 p[8];
        #pragma unroll
        for (int j = 0; j < 8; j++) p[j] = __ldg(&g_cv[e + j]);
        if (active) {
            float4 h[8];
            #pragma unroll
            for (int j = 0; j < 8; j++) h[j] = __ldg(&total[p[j].x * ROW4 + lane]);
            #pragma unroll
            for (int j = 0; j < 8; j++) {
                float v = __int_as_float(p[j].y);
                acc.x += v * h[j].x; acc.y += v * h[j].y;
                acc.z += v * h[j].z; acc.w += v * h[j].w;
            }
        }
    }
    for (; e < end; e++) {
        int2 p0 = __ldg(&g_cv[e]);
        if (active) {
            float v0 = __int_as_float(p0.y);
            float4 a = __ldg(&total[p0.x * ROW4 + lane]);
            acc.x += v0 * a.x; acc.y += v0 * a.y;
            acc.z += v0 * a.z; acc.w += v0 * a.w;
        }
    }
    if (active) out2[w * ROW4 + lane] = acc;
}

// ---------------------------------------------------------------------------
// Inputs (metadata order):
//  0 adj_vals f32[3.2M]   1 u_vals f32[1.6M]   2 embedding f32[100000,100]
//  3 user_embedding f32[40000,100]             4 adj_rows i32  5 adj_cols i32
//  6 u_rows i32  7 u_cols i32  8 user i32[4096]
// Output: concat(total [100000*100], user_all[user] [4096*100]) as f32
// ---------------------------------------------------------------------------
extern "C" void kernel_launch(void* const* d_in, const int* in_sizes, int n_in,
                              void* d_out, int out_size) {
    const float* adj_vals = (const float*)d_in[0];
    const float* u_vals   = (const float*)d_in[1];
    const float* emb      = (const float*)d_in[2];
    const int*   adj_rows = (const int*)d_in[4];
    const int*   adj_cols = (const int*)d_in[5];
    const int*   u_rows   = (const int*)d_in[6];
    const int*   u_cols   = (const int*)d_in[7];
    const int*   user     = (const int*)d_in[8];

    float* total = (float*)d_out;                    // [N_ITEMS*EMB]
    float* out2  = total + (size_t)N_ITEMS * EMB;    // [BATCH*EMB]

    uint2 *eh, *h0, *h1;
    int *cnt, *ptr, *run, *bsum, *uflag;
    cudaGetSymbolAddress((void**)&eh,    g_eh);
    cudaGetSymbolAddress((void**)&h0,    g_h0);
    cudaGetSymbolAddress((void**)&h1,    g_h1);
    cudaGetSymbolAddress((void**)&cnt,   g_cnt);
    cudaGetSymbolAddress((void**)&ptr,   g_ptr);
    cudaGetSymbolAddress((void**)&run,   g_run);
    cudaGetSymbolAddress((void**)&bsum,  g_bsum);
    cudaGetSymbolAddress((void**)&uflag, g_uflag);

    const int TPB = 256;

    // ---- zero histogram + user flags (graph-capturable memset nodes) ----
    cudaMemsetAsync(cnt, 0, N_TOTAL * sizeof(int));
    cudaMemsetAsync(uflag, 0, N_USERS * sizeof(int));
    k_flag<<<(BATCH + TPB - 1) / TPB, TPB>>>(user);

    // ---- fused fp16 conversion + histogram (ungated) ----
    k_prep_hist<<<(NNZ_T + TPB - 1) / TPB, TPB>>>((const float4*)emb,
                                                  adj_rows, u_rows);

    // ---- 2-kernel scan + flag-gated scatter (unified CSR) ----
    k_scan1<<<NB_T, SCAN_TPB>>>(cnt, ptr, bsum, N_TOTAL);
    k_scan23<<<NB_T, SCAN_TPB>>>(ptr, run, bsum, N_TOTAL);
    k_scatter<<<(NNZ_T + TPB - 1) / TPB, TPB>>>(adj_rows, adj_cols, adj_vals,
                                                u_rows, u_cols, u_vals);

    // ---- 3 propagation layers (warp per row, fp16 gathers, fp32 accum) ----
    const int spmm_blocks = (N_ITEMS * 32 + TPB - 1) / TPB;
    k_spmm_h<<<spmm_blocks, TPB>>>(eh, h0);                            // x1
    k_spmm_h<<<spmm_blocks, TPB>>>(h0, h1);                            // x2
    k_spmm_final<<<spmm_blocks, TPB>>>(h1, h0, (const float4*)emb,
                                       (float4*)total);                // total

    // ---- user projection, batch rows only ----
    const int ub_blocks = (BATCH * 32 + TPB - 1) / TPB;
    k_user_batch<<<ub_blocks, TPB>>>((const float4*)total, user, (float4*)out2);
}

// round 17
// speedup vs baseline: 286.2935x; 1.0055x over previous
#include <cuda_runtime.h>
#include <cuda_fp16.h>
#include <cstdint>

// Problem constants (match reference_code)
#define N_ITEMS 100000
#define N_USERS 40000
#define N_TOTAL (N_ITEMS + N_USERS)     // 140000 combined row space
#define EMB     100
#define ROW4    25                      // uint2 (4 halves) per row
#define NNZ_A   3200000
#define NNZ_U   1600000
#define NNZ_T   (NNZ_A + NNZ_U)         // 4.8M combined edges
#define BATCH   4096

#define SCAN_TPB 256
#define NB_T ((N_TOTAL + SCAN_TPB - 1) / SCAN_TPB)   // 547

// ---------------------------------------------------------------------------
// Device scratch (no allocations allowed)
// ---------------------------------------------------------------------------
__device__ uint2 g_eh[(size_t)N_ITEMS * ROW4];  // 20 MB fp16 embedding
__device__ uint2 g_h0[(size_t)N_ITEMS * ROW4];  // 20 MB fp16 x1
__device__ uint2 g_h1[(size_t)N_ITEMS * ROW4];  // 20 MB fp16 x2
__device__ int   g_cnt[N_TOTAL];                // combined histogram
__device__ int   g_ptr[N_TOTAL + 1];            // exclusive offsets + total
__device__ int   g_run[N_TOTAL];                // scatter cursors
__device__ int2  g_cv[NNZ_T];                   // row-sorted (col, val-bits)
__device__ int   g_bsum[1024];
__device__ int   g_uflag[N_USERS];              // user-in-batch flag

// ---------------------------------------------------------------------------
// fused: fp16 embedding conversion + combined histogram + batch-user flags.
// Histogram is UNGATED (hist-gating measured 2x catastrophic: R7, R15).
// Flags are consumed only by k_scatter, which launches after this kernel
// completes (stream order), so fusing the flag writes here is safe.
// g_cnt and g_uflag must be zeroed beforehand (cudaMemsetAsync nodes).
// ---------------------------------------------------------------------------
__global__ void __launch_bounds__(256) k_prep_hist(const float4* __restrict__ emb,
                                                   const int* __restrict__ rowsA,
                                                   const int* __restrict__ rowsU,
                                                   const int* __restrict__ user) {
    int i = blockIdx.x * blockDim.x + threadIdx.x;
    if (i < N_ITEMS * ROW4) {
        float4 v = emb[i];
        __half2 lo = __floats2half2_rn(v.x, v.y);
        __half2 hi = __floats2half2_rn(v.z, v.w);
        uint2 h;
        h.x = *reinterpret_cast<uint32_t*>(&lo);
        h.y = *reinterpret_cast<uint32_t*>(&hi);
        g_eh[i] = h;
    }
    if (i < BATCH) g_uflag[user[i]] = 1;
    if (i < NNZ_A)            atomicAdd(&g_cnt[rowsA[i]], 1);
    else if (i < NNZ_T)       atomicAdd(&g_cnt[N_ITEMS + rowsU[i - NNZ_A]], 1);
}

// ---------------------------------------------------------------------------
// scan phase 1: per-block exclusive scan, block totals into bsum
// ---------------------------------------------------------------------------
__global__ void __launch_bounds__(SCAN_TPB) k_scan1(const int* __restrict__ cnt,
                                                    int* __restrict__ ptr,
                                                    int* __restrict__ bsum, int n) {
    __shared__ int sh[SCAN_TPB];
    int tid = threadIdx.x;
    int i = blockIdx.x * SCAN_TPB + tid;
    int v = (i < n) ? cnt[i] : 0;
    sh[tid] = v;
    __syncthreads();
    for (int off = 1; off < SCAN_TPB; off <<= 1) {
        int t = (tid >= off) ? sh[tid - off] : 0;
        __syncthreads();
        sh[tid] += t;
        __syncthreads();
    }
    if (i < n) ptr[i] = sh[tid] - v;
    if (tid == SCAN_TPB - 1) bsum[blockIdx.x] = sh[tid];
}

// ---------------------------------------------------------------------------
// scan phase 2: each block computes its own prefix over bsum[0..b-1], then
// finalizes its ptr slice and mirrors into run. The last block also writes
// the grand total into ptr[n] so consumers never need an NNZ literal.
// ---------------------------------------------------------------------------
__global__ void __launch_bounds__(SCAN_TPB) k_scan23(int* __restrict__ ptr,
                                                     int* __restrict__ run,
                                                     const int* __restrict__ bsum, int n) {
    __shared__ int sh[SCAN_TPB];
    int tid = threadIdx.x;
    int b   = blockIdx.x;
    int nb  = gridDim.x;

    // inclusive sum over bsum[0..b]; prefix (exclusive of own block) = incl - bsum[b]
    int s = 0;
    for (int t = tid; t <= b; t += SCAN_TPB) s += __ldg(&bsum[t]);
    sh[tid] = s;
    __syncthreads();
    #pragma unroll
    for (int off = SCAN_TPB / 2; off > 0; off >>= 1) {
        if (tid < off) sh[tid] += sh[tid + off];
        __syncthreads();
    }
    int incl   = sh[0];
    int prefix = incl - __ldg(&bsum[b]);

    int i = b * SCAN_TPB + tid;
    if (i < n) {
        int p = ptr[i] + prefix;
        ptr[i] = p;
        run[i] = p;
    }
    if (b == nb - 1 && tid == 0) ptr[n] = incl;   // grand total
}

// ---------------------------------------------------------------------------
// scatter: A edges unconditional; U edges only when their user row is in the
// batch (flag gate skips ~90% of U atomics+stores; unread rows stay stale).
// ---------------------------------------------------------------------------
__global__ void __launch_bounds__(256) k_scatter(
        const int* __restrict__ rowsA, const int* __restrict__ colsA,
        const float* __restrict__ valsA,
        const int* __restrict__ rowsU, const int* __restrict__ colsU,
        const float* __restrict__ valsU) {
    int e = blockIdx.x * blockDim.x + threadIdx.x;
    if (e < NNZ_A) {
        int pos = atomicAdd(&g_run[rowsA[e]], 1);
        g_cv[pos] = make_int2(colsA[e], __float_as_int(valsA[e]));
    } else if (e < NNZ_T) {
        int eu = e - NNZ_A;
        int r  = rowsU[eu];
        if (g_uflag[r]) {
            int pos = atomicAdd(&g_run[N_ITEMS + r], 1);
            g_cv[pos] = make_int2(colsU[eu], __float_as_int(valsU[eu]));
        }
    }
}

// ---------------------------------------------------------------------------
// fp16 helpers
// ---------------------------------------------------------------------------
__device__ __forceinline__ void fma_h4(float4& acc, uint2 h, float v) {
    __half2 lo = *reinterpret_cast<__half2*>(&h.x);
    __half2 hi = *reinterpret_cast<__half2*>(&h.y);
    float2 a = __half22float2(lo);
    float2 b = __half22float2(hi);
    acc.x += v * a.x; acc.y += v * a.y;
    acc.z += v * b.x; acc.w += v * b.y;
}

__device__ __forceinline__ float4 h4_to_f4(uint2 h) {
    __half2 lo = *reinterpret_cast<__half2*>(&h.x);
    __half2 hi = *reinterpret_cast<__half2*>(&h.y);
    float2 a = __half22float2(lo);
    float2 b = __half22float2(hi);
    return make_float4(a.x, a.y, b.x, b.y);
}

// ---------------------------------------------------------------------------
// shared CSR gather loop body (unroll-8, front-batched loads for MLP)
// ---------------------------------------------------------------------------
__device__ __forceinline__ float4 csr_row_gather(const uint2* __restrict__ xh,
                                                 int e, int end, int lane,
                                                 bool active) {
    float4 acc = make_float4(0.f, 0.f, 0.f, 0.f);
    for (; e + 7 < end; e += 8) {
        int2 p[8];
        #pragma unroll
        for (int j = 0; j < 8; j++) p[j] = __ldg(&g_cv[e + j]);
        if (active) {
            uint2 h[8];
            #pragma unroll
            for (int j = 0; j < 8; j++) h[j] = __ldg(&xh[p[j].x * ROW4 + lane]);
            #pragma unroll
            for (int j = 0; j < 8; j++) fma_h4(acc, h[j], __int_as_float(p[j].y));
        }
    }
    if (e + 3 < end) {
        int2 p[4];
        #pragma unroll
        for (int j = 0; j < 4; j++) p[j] = __ldg(&g_cv[e + j]);
        if (active) {
            uint2 h[4];
            #pragma unroll
            for (int j = 0; j < 4; j++) h[j] = __ldg(&xh[p[j].x * ROW4 + lane]);
            #pragma unroll
            for (int j = 0; j < 4; j++) fma_h4(acc, h[j], __int_as_float(p[j].y));
        }
        e += 4;
    }
    for (; e < end; e++) {
        int2 p0 = __ldg(&g_cv[e]);
        if (active) {
            uint2 a = __ldg(&xh[p0.x * ROW4 + lane]);
            fma_h4(acc, a, __int_as_float(p0.y));
        }
    }
    return acc;
}

// ---------------------------------------------------------------------------
// CSR SpMM layers 1,2: warp per row, fp16 in, fp32 accum, fp16 out
// ---------------------------------------------------------------------------
__global__ void __launch_bounds__(256) k_spmm_h(const uint2* __restrict__ xh,
                                                uint2* __restrict__ dsth) {
    int w = (blockIdx.x * blockDim.x + threadIdx.x) >> 5;
    int lane = threadIdx.x & 31;
    if (w >= N_ITEMS) return;

    int e   = __ldg(&g_ptr[w]);
    int end = __ldg(&g_ptr[w + 1]);
    bool active = lane < ROW4;

    float4 acc = csr_row_gather(xh, e, end, lane, active);

    if (active) {
        __half2 lo = __floats2half2_rn(acc.x, acc.y);
        __half2 hi = __floats2half2_rn(acc.z, acc.w);
        uint2 h;
        h.x = *reinterpret_cast<uint32_t*>(&lo);
        h.y = *reinterpret_cast<uint32_t*>(&hi);
        dsth[w * ROW4 + lane] = h;
    }
}

// ---------------------------------------------------------------------------
// Layer 3 (final): acc = A @ x2 ; total = emb + x1 + x2 + acc  (fp32 out)
// ---------------------------------------------------------------------------
__global__ void __launch_bounds__(256) k_spmm_final(const uint2* __restrict__ x2h,
                                                    const uint2* __restrict__ x1h,
                                                    const float4* __restrict__ emb,
                                                    float4* __restrict__ total) {
    int w = (blockIdx.x * blockDim.x + threadIdx.x) >> 5;
    int lane = threadIdx.x & 31;
    if (w >= N_ITEMS) return;

    int e   = __ldg(&g_ptr[w]);
    int end = __ldg(&g_ptr[w + 1]);
    bool active = lane < ROW4;

    float4 acc = csr_row_gather(x2h, e, end, lane, active);

    if (active) {
        int idx = w * ROW4 + lane;
        float4 t  = __ldg(&emb[idx]);
        float4 x1 = h4_to_f4(__ldg(&x1h[idx]));
        float4 x2 = h4_to_f4(__ldg(&x2h[idx]));
        t.x += x1.x + x2.x + acc.x;
        t.y += x1.y + x2.y + acc.y;
        t.z += x1.z + x2.z + acc.z;
        t.w += x1.w + x2.w + acc.w;
        total[idx] = t;
    }
}

// ---------------------------------------------------------------------------
// user batch: out2[b] = sum over CSR row (N_ITEMS + user[b]) of val * total[col]
// fp32 gathers of total, unroll-8 front-batched. ptr[u+1] always valid.
// ---------------------------------------------------------------------------
__global__ void __launch_bounds__(256) k_user_batch(const float4* __restrict__ total,
                                                    const int* __restrict__ user,
                                                    float4* __restrict__ out2) {
    int w = (blockIdx.x * blockDim.x + threadIdx.x) >> 5;
    int lane = threadIdx.x & 31;
    if (w >= BATCH) return;

    int u   = N_ITEMS + __ldg(&user[w]);
    int e   = __ldg(&g_ptr[u]);
    int end = __ldg(&g_ptr[u + 1]);
    bool active = lane < ROW4;

    float4 acc = make_float4(0.f, 0.f, 0.f, 0.f);
    for (; e + 7 < end; e += 8) {
        int2 p[8];
        #pragma unroll
        for (int j = 0; j < 8; j++) p[j] = __ldg(&g_cv[e + j]);
        if (active) {
            float4 h[8];
            #pragma unroll
            for (int j = 0; j < 8; j++) h[j] = __ldg(&total[p[j].x * ROW4 + lane]);
            #pragma unroll
            for (int j = 0; j < 8; j++) {
                float v = __int_as_float(p[j].y);
                acc.x += v * h[j].x; acc.y += v * h[j].y;
                acc.z += v * h[j].z; acc.w += v * h[j].w;
            }
        }
    }
    for (; e < end; e++) {
        int2 p0 = __ldg(&g_cv[e]);
        if (active) {
            float v0 = __int_as_float(p0.y);
            float4 a = __ldg(&total[p0.x * ROW4 + lane]);
            acc.x += v0 * a.x; acc.y += v0 * a.y;
            acc.z += v0 * a.z; acc.w += v0 * a.w;
        }
    }
    if (active) out2[w * ROW4 + lane] = acc;
}

// ---------------------------------------------------------------------------
// Inputs (metadata order):
//  0 adj_vals f32[3.2M]   1 u_vals f32[1.6M]   2 embedding f32[100000,100]
//  3 user_embedding f32[40000,100]             4 adj_rows i32  5 adj_cols i32
//  6 u_rows i32  7 u_cols i32  8 user i32[4096]
// Output: concat(total [100000*100], user_all[user] [4096*100]) as f32
// ---------------------------------------------------------------------------
extern "C" void kernel_launch(void* const* d_in, const int* in_sizes, int n_in,
                              void* d_out, int out_size) {
    const float* adj_vals = (const float*)d_in[0];
    const float* u_vals   = (const float*)d_in[1];
    const float* emb      = (const float*)d_in[2];
    const int*   adj_rows = (const int*)d_in[4];
    const int*   adj_cols = (const int*)d_in[5];
    const int*   u_rows   = (const int*)d_in[6];
    const int*   u_cols   = (const int*)d_in[7];
    const int*   user     = (const int*)d_in[8];

    float* total = (float*)d_out;                    // [N_ITEMS*EMB]
    float* out2  = total + (size_t)N_ITEMS * EMB;    // [BATCH*EMB]

    uint2 *eh, *h0, *h1;
    int *cnt, *ptr, *run, *bsum, *uflag;
    cudaGetSymbolAddress((void**)&eh,    g_eh);
    cudaGetSymbolAddress((void**)&h0,    g_h0);
    cudaGetSymbolAddress((void**)&h1,    g_h1);
    cudaGetSymbolAddress((void**)&cnt,   g_cnt);
    cudaGetSymbolAddress((void**)&ptr,   g_ptr);
    cudaGetSymbolAddress((void**)&run,   g_run);
    cudaGetSymbolAddress((void**)&bsum,  g_bsum);
    cudaGetSymbolAddress((void**)&uflag, g_uflag);

    const int TPB = 256;

    // ---- zero histogram + user flags (graph-capturable memset nodes) ----
    cudaMemsetAsync(cnt, 0, N_TOTAL * sizeof(int));
    cudaMemsetAsync(uflag, 0, N_USERS * sizeof(int));

    // ---- fused fp16 conversion + histogram (ungated) + batch flags ----
    k_prep_hist<<<(NNZ_T + TPB - 1) / TPB, TPB>>>((const float4*)emb,
                                                  adj_rows, u_rows, user);

    // ---- 2-kernel scan + flag-gated scatter (unified CSR) ----
    k_scan1<<<NB_T, SCAN_TPB>>>(cnt, ptr, bsum, N_TOTAL);
    k_scan23<<<NB_T, SCAN_TPB>>>(ptr, run, bsum, N_TOTAL);
    k_scatter<<<(NNZ_T + TPB - 1) / TPB, TPB>>>(adj_rows, adj_cols, adj_vals,
                                                u_rows, u_cols, u_vals);

    // ---- 3 propagation layers (warp per row, fp16 gathers, fp32 accum) ----
    const int spmm_blocks = (N_ITEMS * 32 + TPB - 1) / TPB;
    k_spmm_h<<<spmm_blocks, TPB>>>(eh, h0);                            // x1
    k_spmm_h<<<spmm_blocks, TPB>>>(h0, h1);                            // x2
    k_spmm_final<<<spmm_blocks, TPB>>>(h1, h0, (const float4*)emb,
                                       (float4*)total);                // total

    // ---- user projection, batch rows only ----
    const int ub_blocks = (BATCH * 32 + TPB - 1) / TPB;
    k_user_batch<<<ub_blocks, TPB>>>((const float4*)total, user, (float4*)out2);
}